// round 3
// baseline (speedup 1.0000x reference)
#include <cuda_runtime.h>
#include <cstdint>

#define N_NODES 100000
#define N_EDGES 1600000
#define SCAN_BLOCKS 98   // ceil(100000/1024)

// -------- device scratch (static: no allocations allowed) --------
__device__ int   g_deg[N_NODES];
__device__ int   g_rowptr[N_NODES + 1];
__device__ int   g_cursor[N_NODES];
__device__ int   g_col[N_EDGES];
__device__ int   g_bsum[128];
__device__ __align__(16) float g_z1[N_NODES * 64];
__device__ __align__(16) float g_mid[N_NODES * 128];
__device__ __align__(16) float g_h1[N_NODES * 128];
__device__ __align__(16) float g_z2[N_NODES * 128];

// Compile-time scratch-buffer binding (no host-side symbol addressing).
template <int ID>
__device__ __forceinline__ float* buf() {
    if constexpr (ID == 0)      return g_z1;
    else if constexpr (ID == 1) return g_mid;
    else if constexpr (ID == 2) return g_h1;
    else                        return g_z2;
}

// -------- f32x2 packed-FMA helpers (sm_103a) --------
__device__ __forceinline__ unsigned long long pack2(float a, float b) {
    unsigned long long r;
    asm("mov.b64 %0, {%1, %2};" : "=l"(r) : "f"(a), "f"(b));
    return r;
}
__device__ __forceinline__ void fma2(unsigned long long& d,
                                     unsigned long long a,
                                     unsigned long long b) {
    asm("fma.rn.f32x2 %0, %1, %2, %0;" : "+l"(d) : "l"(a), "l"(b));
}
__device__ __forceinline__ float2 unpack2(unsigned long long v) {
    float2 r;
    asm("mov.b64 {%0, %1}, %2;" : "=f"(r.x), "=f"(r.y) : "l"(v));
    return r;
}

// ==================== CSR build ====================
// edge_index arrives as int32 (harness dtype set: float32/int32/bf16).
// Layout row-major (2, E): src = ei[e], dst = ei[E + e].

__global__ void k_zero_deg() {
    int i = blockIdx.x * 256 + threadIdx.x;
    if (i < N_NODES) g_deg[i] = 0;
}

__global__ void k_degree(const int* __restrict__ ei) {
    int e = blockIdx.x * 256 + threadIdx.x;
    if (e < N_EDGES) atomicAdd(&g_deg[ei[N_EDGES + e]], 1);
}

__global__ void k_scan1() {
    __shared__ int s[1024];
    int t = threadIdx.x;
    int i = blockIdx.x * 1024 + t;
    int v = (i < N_NODES) ? g_deg[i] : 0;
    s[t] = v;
    __syncthreads();
#pragma unroll
    for (int off = 1; off < 1024; off <<= 1) {
        int tmp = (t >= off) ? s[t - off] : 0;
        __syncthreads();
        s[t] += tmp;
        __syncthreads();
    }
    if (i < N_NODES) g_rowptr[i] = s[t] - v;   // exclusive within block
    if (t == 1023) g_bsum[blockIdx.x] = s[1023];
}

__global__ void k_scan2() {
    if (threadIdx.x == 0) {
        int acc = 0;
        for (int b = 0; b < SCAN_BLOCKS; b++) {
            int t = g_bsum[b];
            g_bsum[b] = acc;
            acc += t;
        }
    }
}

__global__ void k_scan3() {
    int i = blockIdx.x * 256 + threadIdx.x;
    if (i < N_NODES) {
        int r = g_rowptr[i] + g_bsum[i >> 10];
        g_rowptr[i] = r;
        g_cursor[i] = r;
    }
    if (i == 0) g_rowptr[N_NODES] = N_EDGES;
}

__global__ void k_fill(const int* __restrict__ ei) {
    int e = blockIdx.x * 256 + threadIdx.x;
    if (e < N_EDGES) {
        int d = ei[N_EDGES + e];
        int s = ei[e];
        int p = atomicAdd(&g_cursor[d], 1);
        g_col[p] = s;
    }
}

// ==================== Aggregation (gather, atomic-free) ====================
// z[i] = x[i] + sum_{j in neigh_in(i)} x[j]

// d=64: warp per node; 16 lanes cover 16 float4; two half-warps process
// alternating edges, combined with shfl at the end. Writes g_z1.
__global__ void __launch_bounds__(256) k_agg64(const float* __restrict__ x) {
    int node = (blockIdx.x * 256 + threadIdx.x) >> 5;   // exactly N_NODES warps
    int lane = threadIdx.x & 31;
    int c = lane & 15;
    int h = lane >> 4;
    int beg = g_rowptr[node], end = g_rowptr[node + 1];
    float4 acc = make_float4(0.f, 0.f, 0.f, 0.f);
    const float4* x4 = (const float4*)x;
    for (int p = beg + h; p < end; p += 2) {
        int s = __ldg(&g_col[p]);
        float4 v = x4[s * 16 + c];
        acc.x += v.x; acc.y += v.y; acc.z += v.z; acc.w += v.w;
    }
    acc.x += __shfl_xor_sync(0xffffffffu, acc.x, 16);
    acc.y += __shfl_xor_sync(0xffffffffu, acc.y, 16);
    acc.z += __shfl_xor_sync(0xffffffffu, acc.z, 16);
    acc.w += __shfl_xor_sync(0xffffffffu, acc.w, 16);
    if (h == 0) {
        float4 xi = x4[node * 16 + c];
        float4 r = make_float4(xi.x + acc.x, xi.y + acc.y,
                               xi.z + acc.z, xi.w + acc.w);
        ((float4*)g_z1)[node * 16 + c] = r;
    }
}

// d=128: warp per node; 32 lanes cover 32 float4. Reads g_h1, writes g_z2.
__global__ void __launch_bounds__(256) k_agg128() {
    int node = (blockIdx.x * 256 + threadIdx.x) >> 5;
    int lane = threadIdx.x & 31;
    int beg = g_rowptr[node], end = g_rowptr[node + 1];
    const float4* h4 = (const float4*)g_h1;
    float4 a0 = make_float4(0.f, 0.f, 0.f, 0.f);
    float4 a1 = make_float4(0.f, 0.f, 0.f, 0.f);
    int p = beg;
    for (; p + 1 < end; p += 2) {
        int s0 = __ldg(&g_col[p]);
        int s1 = __ldg(&g_col[p + 1]);
        float4 v0 = h4[s0 * 32 + lane];
        float4 v1 = h4[s1 * 32 + lane];
        a0.x += v0.x; a0.y += v0.y; a0.z += v0.z; a0.w += v0.w;
        a1.x += v1.x; a1.y += v1.y; a1.z += v1.z; a1.w += v1.w;
    }
    if (p < end) {
        int s0 = __ldg(&g_col[p]);
        float4 v0 = h4[s0 * 32 + lane];
        a0.x += v0.x; a0.y += v0.y; a0.z += v0.z; a0.w += v0.w;
    }
    float4 hi = h4[node * 32 + lane];
    float4 r = make_float4(hi.x + a0.x + a1.x, hi.y + a0.y + a1.y,
                           hi.z + a0.z + a1.z, hi.w + a0.w + a1.w);
    ((float4*)g_z2)[node * 32 + lane] = r;
}

// ==================== Dense layer: out = act(in @ W + b) ====================
// BLOCK_M = 64 nodes per block, full NOUT. 256 threads.
// IN_ID / OUT_ID select scratch buffers at compile time; OUT_ID=-1 -> ext out.
template <int K, int NOUT, bool RELU, int IN_ID, int OUT_ID>
__global__ void __launch_bounds__(256, 2)
k_linear(const float* __restrict__ W, const float* __restrict__ bias,
         float* __restrict__ ext_out, int n) {
    constexpr int TX = NOUT / 4;     // 32 (NOUT=128) or 16 (NOUT=64)
    constexpr int TY = 256 / TX;     // 8 or 16
    constexpr int TM = 64 / TY;      // 8 or 4
    constexpr int AS = K + 4;        // padded A row stride (float4-aligned)
    constexpr int K4 = K / 4;

    const float* in = buf<IN_ID>();
    float* out = (OUT_ID < 0) ? ext_out : buf<(OUT_ID < 0) ? 0 : OUT_ID>();

    extern __shared__ float sm[];
    float* Ws = sm;                  // K * NOUT
    float* As = sm + K * NOUT;       // 64 * AS

    int t = threadIdx.x;
    int m0 = blockIdx.x * 64;

    // Load weights (coalesced float4 copy)
    for (int i = t; i < K * NOUT / 4; i += 256)
        ((float4*)Ws)[i] = ((const float4*)W)[i];

    // Load A tile (zero-fill rows past n)
    for (int i = t; i < 64 * K4; i += 256) {
        int m = i / K4, k4 = i % K4;
        float4 v = make_float4(0.f, 0.f, 0.f, 0.f);
        if (m0 + m < n) v = ((const float4*)in)[(m0 + m) * K4 + k4];
        *((float4*)&As[m * AS + k4 * 4]) = v;
    }
    __syncthreads();

    int tx = t % TX, ty = t / TX;
    unsigned long long acc[TM][2];
#pragma unroll
    for (int i = 0; i < TM; i++) { acc[i][0] = 0ull; acc[i][1] = 0ull; }

#pragma unroll 8
    for (int k = 0; k < K; k++) {
        float4 w = ((const float4*)Ws)[k * TX + tx];
        unsigned long long w01 = pack2(w.x, w.y);
        unsigned long long w23 = pack2(w.z, w.w);
#pragma unroll
        for (int i = 0; i < TM; i++) {
            float a = As[(ty * TM + i) * AS + k];
            unsigned long long aa = pack2(a, a);
            fma2(acc[i][0], aa, w01);
            fma2(acc[i][1], aa, w23);
        }
    }

    float4 bb = ((const float4*)bias)[tx];
#pragma unroll
    for (int i = 0; i < TM; i++) {
        int m = m0 + ty * TM + i;
        if (m < n) {
            float2 p0 = unpack2(acc[i][0]);
            float2 p1 = unpack2(acc[i][1]);
            float4 r = make_float4(p0.x + bb.x, p0.y + bb.y,
                                   p1.x + bb.z, p1.y + bb.w);
            if (RELU) {
                r.x = fmaxf(r.x, 0.f); r.y = fmaxf(r.y, 0.f);
                r.z = fmaxf(r.z, 0.f); r.w = fmaxf(r.w, 0.f);
            }
            ((float4*)out)[m * (NOUT / 4) + tx] = r;
        }
    }
}

// ==================== host orchestration ====================

static inline int smem_bytes(int K, int NOUT) {
    return (K * NOUT + 64 * (K + 4)) * 4;
}

extern "C" void kernel_launch(void* const* d_in, const int* in_sizes, int n_in,
                              void* d_out, int out_size) {
    const float*      x    = (const float*)d_in[0];
    const int*        ei   = (const int*)d_in[1];     // int32 (2, E) row-major
    const float*      W1a  = (const float*)d_in[2];
    const float*      b1a  = (const float*)d_in[3];
    const float*      W1b  = (const float*)d_in[4];
    const float*      b1b  = (const float*)d_in[5];
    const float*      W2a  = (const float*)d_in[6];
    const float*      b2a  = (const float*)d_in[7];
    const float*      W2b  = (const float*)d_in[8];
    const float*      b2b  = (const float*)d_in[9];
    const float*      Wlin = (const float*)d_in[10];
    const float*      blin = (const float*)d_in[11];
    float*            out  = (float*)d_out;

    const int S1 = smem_bytes(64, 128);    // 50176
    const int S2 = smem_bytes(128, 128);   // 99328
    const int S3 = smem_bytes(128, 64);    // 66560
    cudaFuncSetAttribute(k_linear<64, 128, true, 0, 1>,
                         cudaFuncAttributeMaxDynamicSharedMemorySize, S1);
    cudaFuncSetAttribute(k_linear<128, 128, true, 1, 2>,
                         cudaFuncAttributeMaxDynamicSharedMemorySize, S2);
    cudaFuncSetAttribute(k_linear<128, 128, true, 3, 1>,
                         cudaFuncAttributeMaxDynamicSharedMemorySize, S2);
    cudaFuncSetAttribute(k_linear<128, 64, false, 2, -1>,
                         cudaFuncAttributeMaxDynamicSharedMemorySize, S3);

    const int GN  = (N_NODES + 255) / 256;   // 391
    const int GE  = (N_EDGES + 255) / 256;   // 6250
    const int GW  = N_NODES / 8;             // 12500 (warp per node, 8 warps/block)
    const int GL  = (N_NODES + 63) / 64;     // 1563

    // --- CSR build (by dst) ---
    k_zero_deg<<<GN, 256>>>();
    k_degree<<<GE, 256>>>(ei);
    k_scan1<<<SCAN_BLOCKS, 1024>>>();
    k_scan2<<<1, 32>>>();
    k_scan3<<<GN, 256>>>();
    k_fill<<<GE, 256>>>(ei);

    // --- conv1 ---
    k_agg64<<<GW, 256>>>(x);
    k_linear<64, 128, true, 0, 1><<<GL, 256, S1>>>(W1a, b1a, nullptr, N_NODES);
    k_linear<128, 128, true, 1, 2><<<GL, 256, S2>>>(W1b, b1b, nullptr, N_NODES);

    // --- conv2 ---
    k_agg128<<<GW, 256>>>();
    k_linear<128, 128, true, 3, 1><<<GL, 256, S2>>>(W2a, b2a, nullptr, N_NODES);
    k_linear<128, 128, true, 1, 2><<<GL, 256, S2>>>(W2b, b2b, nullptr, N_NODES);

    // --- final projection ---
    k_linear<128, 64, false, 2, -1><<<GL, 256, S3>>>(Wlin, blin, out, N_NODES);
}